// round 11
// baseline (speedup 1.0000x reference)
#include <cuda_runtime.h>

#define T_STEPS 1000
#define B_TOT   256
#define FIN     39
#define H       100
#define G3      300
#define NCLS    20
#define GSTR    (B_TOT * G3)
#define NPROD   20
#define NREC    128
#define NCTAS   (NREC + NPROD)

typedef unsigned long long u64;

// 307 MB scratch for precomputed input gates gi[t][b][g] (includes b_ih)
__device__ float g_gi[(size_t)T_STEPS * B_TOT * G3];
// producer progress: g_flagi[p] = count of finished t's with t%NPROD==p
__device__ int g_flagi[NPROD];
// all-CTA completion counter (for end-of-launch flag reset)
__device__ int g_done;

__device__ __forceinline__ u64 pk(float x, float y) {
    u64 r; asm("mov.b64 %0,{%1,%2};" : "=l"(r) : "f"(x), "f"(y)); return r;
}
__device__ __forceinline__ void fma2(u64 &d, u64 a, u64 b) {
    asm("fma.rn.f32x2 %0,%1,%2,%0;" : "+l"(d) : "l"(a), "l"(b));
}
__device__ __forceinline__ u64 add2(u64 a, u64 b) {
    u64 r; asm("add.rn.f32x2 %0,%1,%2;" : "=l"(r) : "l"(a), "l"(b)); return r;
}
__device__ __forceinline__ float hsum2(u64 a) {
    float x, y; asm("mov.b64 {%0,%1},%2;" : "=f"(x), "=f"(y) : "l"(a)); return x + y;
}
__device__ __forceinline__ void lds_v2u64(u64 &a, u64 &b, unsigned addr) {
    asm volatile("ld.shared.v2.u64 {%0,%1},[%2];" : "=l"(a), "=l"(b) : "r"(addr));
}
__device__ __forceinline__ float sigf(float x) {
    return __fdividef(1.0f, 1.0f + __expf(-x));
}
__device__ __forceinline__ float tanh_acc(float x) {
    return 2.0f * sigf(2.0f * x) - 1.0f;
}

// wait until ALL gi(t') for t' <= tneed (clamped) are published:
// for each residue p, need flag[p] >= floor((tneed-p)/NPROD)+1
__device__ __forceinline__ void wait_gi(int tneed) {
    if (tneed > T_STEPS - 1) tneed = T_STEPS - 1;
    #pragma unroll
    for (int p = 0; p < NPROD; p++) {
        int cnt = (tneed >= p) ? ((tneed - p) / NPROD + 1) : 0;
        if (cnt > 0) {
            volatile int* f = g_flagi + p;
            while (*f < cnt) { __nanosleep(64); }
        }
    }
    __threadfence();   // acquire: order subsequent gi reads after flag observation
}

#define CH  28          // rec chunk floats (112B, 16B-aligned, conflict-free banks)
#define HP  112         // padded h floats per batch

__global__ void __launch_bounds__(400, 1) gru_fused_kernel(
    const float* __restrict__ mfcc0, const float* __restrict__ mfcc1,
    const float* __restrict__ mfcc2, const float* __restrict__ len0,
    const float* __restrict__ W_ih, const float* __restrict__ W_hh,
    const float* __restrict__ b_ih, const float* __restrict__ b_hh,
    const float* __restrict__ W_out, const float* __restrict__ b_out,
    float* __restrict__ out)
{
    __shared__ __align__(16) float xt[32][40];       // producer x tile
    __shared__ __align__(16) float h_sh[2][2][HP];   // rec: [buf][batch][v]
    __shared__ float feat_sh[2][2 * H];

    const int tid = threadIdx.x;

    // =====================================================================
    // PRODUCER CTAs: blockIdx 128..147, residue p = blockIdx-128
    // gi[t][b][g] = b_ih[g] + sum_k x[t][b][k] * W_ih[g][k]
    // =====================================================================
    if (blockIdx.x >= NREC) {
        const int p = blockIdx.x - NREC;
        const int g = (tid < G3) ? tid : (G3 - 1);

        u64 wih[20];
        {
            const float* wi = W_ih + g * FIN;
            #pragma unroll
            for (int j = 0; j < 19; j++) wih[j] = pk(wi[2 * j], wi[2 * j + 1]);
            wih[19] = pk(wi[38], 0.0f);
        }
        const float bias = b_ih[g];
        const unsigned xB = (unsigned)__cvta_generic_to_shared(&xt[0][0]);

        for (int t = p; t < T_STEPS; t += NPROD) {
            const int pbase = t * B_TOT;
            for (int tile = 0; tile < B_TOT / 32; tile++) {
                __syncthreads();     // protect xt reuse
                for (int i = tid; i < 32 * 40; i += 400) {
                    int pr = i / 40, k = i - pr * 40;
                    float v = 0.0f;
                    if (k < 39) {
                        const float* src = (k < 13) ? mfcc0 : (k < 26) ? mfcc1 : mfcc2;
                        int f = (k < 13) ? k : (k < 26) ? (k - 13) : (k - 26);
                        v = src[(size_t)(pbase + tile * 32 + pr) * 13 + f];
                    }
                    xt[pr][k] = v;
                }
                __syncthreads();

                const int pb = pbase + tile * 32;
                #pragma unroll 2
                for (int pair = 0; pair < 32; pair += 2) {
                    u64 a0 = 0, a1 = 0, c0 = 0, c1 = 0;
                    unsigned ad = xB + pair * 160;
                    #pragma unroll
                    for (int j = 0; j < 10; j++) {
                        u64 q, r, q2, r2;
                        lds_v2u64(q,  r,  ad + j * 16);
                        lds_v2u64(q2, r2, ad + 160 + j * 16);
                        fma2(a0, wih[2 * j],     q);
                        fma2(a1, wih[2 * j + 1], r);
                        fma2(c0, wih[2 * j],     q2);
                        fma2(c1, wih[2 * j + 1], r2);
                    }
                    if (tid < G3) {
                        g_gi[(size_t)(pb + pair) * G3 + g]     = hsum2(add2(a0, a1)) + bias;
                        g_gi[(size_t)(pb + pair + 1) * G3 + g] = hsum2(add2(c0, c1)) + bias;
                    }
                }
            }
            __syncthreads();
            if (tid == 0) {
                __threadfence();                 // release: gi stores before flag
                atomicAdd(&g_flagi[p], 1);
            }
        }
        // participate in global done-count (reset happens after ALL CTAs done)
        __syncthreads();
        if (tid == 0) {
            int d = atomicAdd(&g_done, 1);
            if (d == NCTAS - 1) {
                #pragma unroll
                for (int i = 0; i < NPROD; i++) g_flagi[i] = 0;
                __threadfence();
                g_done = 0;
            }
        }
        return;
    }

    // =====================================================================
    // RECURRENT CTAs: blockIdx 0..127 — R3 kernel + frontier waits.
    // thread = (h = tid>>2, chunk c = tid&3), CH=28 (zero-padded), 2 batches.
    // Quad bfly-reduction; lanes c<2 finalize batch b=c in registers.
    // h double-buffered -> 1 barrier/step.
    // =====================================================================
    const int h   = tid >> 2;          // 0..99
    const int c   = tid & 3;           // K-chunk, and batch selector for c<2
    const int b0  = blockIdx.x * 2;
    const unsigned smask = (tid < 384) ? 0xFFFFFFFFu : 0x0000FFFFu;

    // zero h (incl pads)
    for (int i = tid; i < 2 * 2 * HP; i += 400) ((float*)h_sh)[i] = 0.0f;

    // persistent W_hh chunk rows for 3 gates (r,z,n), zero-padded
    const int k0   = c * CH;
    const int kcnt = (k0 + CH <= H) ? CH : (H - k0);   // 28 or 16
    u64 w[3][CH / 2];
    #pragma unroll
    for (int i = 0; i < 3; i++) {
        const float* wr = W_hh + (h + i * H) * H + k0;
        #pragma unroll
        for (int j = 0; j < CH / 2; j++) {
            float x0 = (2 * j     < kcnt) ? wr[2 * j]     : 0.0f;
            float x1 = (2 * j + 1 < kcnt) ? wr[2 * j + 1] : 0.0f;
            w[i][j] = pk(x0, x1);
        }
    }

    // finalize-lane state (c < 2, batch b = c)
    const bool fin = (c < 2);
    float bh0 = 0.0f, bh1 = 0.0f, bh2 = 0.0f;
    const float* gp = g_gi;
    if (fin) {
        bh0 = b_hh[h]; bh1 = b_hh[h + H]; bh2 = b_hh[h + 2 * H];
        gp = g_gi + (size_t)(b0 + c) * G3 + h;
    }
    float hprev = 0.0f, hs = 0.0f, hm = -1e30f;

    // wait for gi(0..16) before first reads
    if (tid == 0) wait_gi(16);
    __syncthreads();

    // prefetch gi(t=0) — L2-coherent loads (producer wrote from another SM)
    float gv0 = 0.0f, gv1 = 0.0f, gv2 = 0.0f;
    if (fin) { gv0 = __ldcg(gp); gv1 = __ldcg(gp + H); gv2 = __ldcg(gp + 2 * H); }

    const unsigned hB = (unsigned)__cvta_generic_to_shared(&h_sh[0][0][0]) + c * (CH * 4);
    int bp = 0;

    for (int t = 0; t < T_STEPS; t++) {
        // prefetch gi(t+1) ~1.5 steps before use
        float gn0 = 0.0f, gn1 = 0.0f, gn2 = 0.0f;
        if (fin && t + 1 < T_STEPS) {
            const float* gq = gp + (size_t)(t + 1) * GSTR;
            gn0 = __ldcg(gq); gn1 = __ldcg(gq + H); gn2 = __ldcg(gq + 2 * H);
        }

        // partial dots: 3 gates x 2 batches, 2 accumulators each
        u64 a00 = 0, a01 = 0, a10 = 0, a11 = 0, a20 = 0, a21 = 0;   // batch 0
        u64 d00 = 0, d01 = 0, d10 = 0, d11 = 0, d20 = 0, d21 = 0;   // batch 1
        {
            const unsigned ad = hB + bp * (2 * HP * 4);
            #pragma unroll
            for (int j = 0; j < CH / 4; j++) {           // 7 iters, 16B each
                u64 q0, q1, r0, r1;
                lds_v2u64(q0, q1, ad + j * 16);                  // batch 0
                lds_v2u64(r0, r1, ad + HP * 4 + j * 16);         // batch 1
                fma2(a00, w[0][2 * j], q0); fma2(a01, w[0][2 * j + 1], q1);
                fma2(a10, w[1][2 * j], q0); fma2(a11, w[1][2 * j + 1], q1);
                fma2(a20, w[2][2 * j], q0); fma2(a21, w[2][2 * j + 1], q1);
                fma2(d00, w[0][2 * j], r0); fma2(d01, w[0][2 * j + 1], r1);
                fma2(d10, w[1][2 * j], r0); fma2(d11, w[1][2 * j + 1], r1);
                fma2(d20, w[2][2 * j], r0); fma2(d21, w[2][2 * j + 1], r1);
            }
        }
        float s0b0 = hsum2(add2(a00, a01));
        float s1b0 = hsum2(add2(a10, a11));
        float s2b0 = hsum2(add2(a20, a21));
        float s0b1 = hsum2(add2(d00, d01));
        float s1b1 = hsum2(add2(d10, d11));
        float s2b1 = hsum2(add2(d20, d21));

        // quad reduction over chunks
        s0b0 += __shfl_xor_sync(smask, s0b0, 1); s0b0 += __shfl_xor_sync(smask, s0b0, 2);
        s1b0 += __shfl_xor_sync(smask, s1b0, 1); s1b0 += __shfl_xor_sync(smask, s1b0, 2);
        s2b0 += __shfl_xor_sync(smask, s2b0, 1); s2b0 += __shfl_xor_sync(smask, s2b0, 2);
        s0b1 += __shfl_xor_sync(smask, s0b1, 1); s0b1 += __shfl_xor_sync(smask, s0b1, 2);
        s1b1 += __shfl_xor_sync(smask, s1b1, 1); s1b1 += __shfl_xor_sync(smask, s1b1, 2);
        s2b1 += __shfl_xor_sync(smask, s2b1, 1); s2b1 += __shfl_xor_sync(smask, s2b1, 2);

        if (fin) {
            float hr = (c == 0) ? s0b0 : s0b1;
            float hz = (c == 0) ? s1b0 : s1b1;
            float hn = (c == 0) ? s2b0 : s2b1;
            float r = sigf(gv0 + hr + bh0);
            float z = sigf(gv1 + hz + bh1);
            float n = tanh_acc(gv2 + r * (hn + bh2));
            float hnew = n + z * (hprev - n);
            hprev = hnew;
            hs += hnew;
            hm = fmaxf(hm, hnew);
            h_sh[1 - bp][c][h] = hnew;
        }
        gv0 = gn0; gv1 = gn1; gv2 = gn2;

        // frontier check every 16 steps: cover prefetches through gi(t+17)
        if ((t & 15) == 15 && tid == 0) wait_gi(t + 17);
        __syncthreads();
        bp ^= 1;
    }

    // pooling features
    if (fin) {
        float inv = 1.0f / len0[b0 + c];
        feat_sh[c][h]     = hs * inv;
        feat_sh[c][H + h] = hm;
    }
    __syncthreads();

    // output linear: [2 x 20] = feat[2 x 200] @ W_out^T + b_out
    if (tid < 2 * NCLS) {
        int bb = tid / NCLS, cc = tid % NCLS;
        const float* wr = W_out + cc * 2 * H;
        float acc = b_out[cc];
        #pragma unroll 4
        for (int j = 0; j < 2 * H; j++) acc += feat_sh[bb][j] * wr[j];
        out[(b0 + bb) * NCLS + cc] = acc;
    }
    __syncthreads();

    // last CTA overall (rec or producer) resets flags for the next replay
    if (tid == 0) {
        int d = atomicAdd(&g_done, 1);
        if (d == NCTAS - 1) {
            #pragma unroll
            for (int i = 0; i < NPROD; i++) g_flagi[i] = 0;
            __threadfence();
            g_done = 0;
        }
    }
}

extern "C" void kernel_launch(void* const* d_in, const int* in_sizes, int n_in,
                              void* d_out, int out_size)
{
    const float* mfcc0 = (const float*)d_in[0];
    const float* mfcc1 = (const float*)d_in[1];
    const float* mfcc2 = (const float*)d_in[2];
    const float* len0  = (const float*)d_in[3];
    const float* W_ih  = (const float*)d_in[4];
    const float* W_hh  = (const float*)d_in[5];
    const float* b_ih  = (const float*)d_in[6];
    const float* b_hh  = (const float*)d_in[7];
    const float* W_out = (const float*)d_in[8];
    const float* b_out = (const float*)d_in[9];
    float* out = (float*)d_out;

    gru_fused_kernel<<<NCTAS, 400>>>(mfcc0, mfcc1, mfcc2, len0,
                                     W_ih, W_hh, b_ih, b_hh,
                                     W_out, b_out, out);
}

// round 13
// speedup vs baseline: 1.1697x; 1.1697x over previous
#include <cuda_runtime.h>

#define T_STEPS 1000
#define B_TOT   256
#define FIN     39
#define H       100
#define G3      300
#define NCLS    20

typedef unsigned long long u64;

__device__ __forceinline__ u64 pk(float x, float y) {
    u64 r; asm("mov.b64 %0,{%1,%2};" : "=l"(r) : "f"(x), "f"(y)); return r;
}
__device__ __forceinline__ void fma2(u64 &d, u64 a, u64 b) {
    asm("fma.rn.f32x2 %0,%1,%2,%0;" : "+l"(d) : "l"(a), "l"(b));
}
__device__ __forceinline__ float hsum2(u64 a) {
    float x, y; asm("mov.b64 {%0,%1},%2;" : "=f"(x), "=f"(y) : "l"(a)); return x + y;
}
__device__ __forceinline__ void lds_v2u64(u64 &a, u64 &b, unsigned addr) {
    asm volatile("ld.shared.v2.u64 {%0,%1},[%2];" : "=l"(a), "=l"(b) : "r"(addr));
}
__device__ __forceinline__ void lds_u64(u64 &a, unsigned addr) {
    asm volatile("ld.shared.u64 %0,[%1];" : "=l"(a) : "r"(addr));
}
__device__ __forceinline__ float sigf(float x) {
    return __fdividef(1.0f, 1.0f + __expf(-x));
}
__device__ __forceinline__ float tanh_acc(float x) {
    return 2.0f * sigf(2.0f * x) - 1.0f;
}

// ---------------------------------------------------------------------------
// Single fused kernel: 128 CTAs x 400 threads, each CTA owns 2 batches for all
// 1000 steps AND computes its own input-gate projections gi on the fly.
//
// thread = (h = tid>>2, c = tid&3).
//   h-dot:  W_hh chunk [c*28, c*28+28) x 3 gates, both batches (84 fma2/step)
//   gi:     W_ih K-quarter [c*10, c*10+10) x 3 gates, both batches (30 fma2/step)
//           computed ONE step ahead from x staged in smem; 6-SHFL role butterfly
//           lands gi(t+1)[r,z,n] for batch c directly in finalize lane c's regs.
//   h-dot reduce: 12 SHFL quad butterfly; lanes c<2 finalize batch b=c.
// x(t+2) staged per step by 78 loader threads (double-buffered, 80B slots).
// h double-buffered -> 1 barrier/step. No global scratch at all.
// Quarter reads: v2u64 @+0, v2u64 @+16, u64 @+32 (all aligned).
// ---------------------------------------------------------------------------
#define CH  28          // h-dot chunk floats (112B stride: aligned + conflict-free)
#define HP  112         // padded h floats per batch
#define XS  80          // x floats per batch (4 slots x 20; quarter c at c*20)

__global__ void __launch_bounds__(400, 1) gru_fused_kernel(
    const float* __restrict__ mfcc0, const float* __restrict__ mfcc1,
    const float* __restrict__ mfcc2, const float* __restrict__ len0,
    const float* __restrict__ W_ih, const float* __restrict__ W_hh,
    const float* __restrict__ b_ih, const float* __restrict__ b_hh,
    const float* __restrict__ W_out, const float* __restrict__ b_out,
    float* __restrict__ out)
{
    __shared__ __align__(16) float h_sh[2][2][HP];   // [buf][batch][v]
    __shared__ __align__(16) float x_sh[2][2][XS];   // [buf][batch][slots]
    __shared__ float feat_sh[2][2 * H];

    const int tid = threadIdx.x;
    const int h   = tid >> 2;          // 0..99
    const int c   = tid & 3;           // chunk/quarter; batch selector for c<2
    const int b0  = blockIdx.x * 2;
    const unsigned smask = (tid < 384) ? 0xFFFFFFFFu : 0x0000FFFFu;

    // zero h buffers and x buffers (incl pad floats)
    for (int i = tid; i < 2 * 2 * HP; i += 400) ((float*)h_sh)[i] = 0.0f;
    for (int i = tid; i < 2 * 2 * XS; i += 400) ((float*)x_sh)[i] = 0.0f;

    // ---- persistent W_hh chunk rows for 3 gates (r,z,n), zero-padded ----
    const int k0   = c * CH;
    const int kcnt = (k0 + CH <= H) ? CH : (H - k0);   // 28 or 16
    u64 w[3][CH / 2];
    #pragma unroll
    for (int i = 0; i < 3; i++) {
        const float* wr = W_hh + (h + i * H) * H + k0;
        #pragma unroll
        for (int j = 0; j < CH / 2; j++) {
            float x0 = (2 * j     < kcnt) ? wr[2 * j]     : 0.0f;
            float x1 = (2 * j + 1 < kcnt) ? wr[2 * j + 1] : 0.0f;
            w[i][j] = pk(x0, x1);
        }
    }

    // ---- persistent W_ih K-quarter for 3 gates (10 floats each, padded) ----
    const int q0 = c * 10;
    u64 wi[3][5];
    #pragma unroll
    for (int i = 0; i < 3; i++) {
        const float* wr = W_ih + (h + i * H) * FIN;
        #pragma unroll
        for (int j = 0; j < 5; j++) {
            int k = q0 + 2 * j;
            float x0 = (k     < FIN) ? wr[k]     : 0.0f;
            float x1 = (k + 1 < FIN) ? wr[k + 1] : 0.0f;
            wi[i][j] = pk(x0, x1);
        }
    }

    // finalize-lane constants (c<2, batch bl=c): gi biases fold b_ih + b_hh(r,z)
    const bool fin = (c < 2);
    float bi0 = 0.0f, bi1 = 0.0f, bi2 = 0.0f, bh2 = 0.0f;
    if (fin) {
        bi0 = b_ih[h]         + b_hh[h];
        bi1 = b_ih[h + H]     + b_hh[h + H];
        bi2 = b_ih[h + 2 * H];
        bh2 = b_hh[h + 2 * H];
    }

    // ---- x loader threads: tid in [200, 278): one (batch, feature) each ----
    const bool xl = (tid >= 200 && tid < 200 + 2 * FIN);
    const float* xbase = mfcc0;
    int xpos = 0, xlb = 0;
    if (xl) {
        int li = tid - 200; xlb = li / FIN; int lk = li % FIN;
        const float* src = (lk < 13) ? mfcc0 : (lk < 26) ? mfcc1 : mfcc2;
        int f = (lk < 13) ? lk : (lk < 26) ? (lk - 13) : (lk - 26);
        xbase = src + (size_t)(b0 + xlb) * 13 + f;
        int qq = lk / 10;
        xpos = qq * 20 + (lk - qq * 10);
    }
    const int XSTRIDE = B_TOT * 13;

    // prologue: stage x(0) -> buf0, x(1) -> buf1
    if (xl) {
        x_sh[0][xlb][xpos] = __ldg(xbase);
        x_sh[1][xlb][xpos] = __ldg(xbase + XSTRIDE);
    }
    __syncthreads();

    const unsigned hB = (unsigned)__cvta_generic_to_shared(&h_sh[0][0][0]) + c * (CH * 4);
    const unsigned xB = (unsigned)__cvta_generic_to_shared(&x_sh[0][0][0]) + c * 80;

    // gi compute: partials for both batches from x buf; aligned reads only
    auto gi_compute = [&](int buf, float &g0, float &g1, float &g2) {
        u64 p0 = 0, p1 = 0, p2 = 0;        // batch 0: r,z,n
        u64 s0 = 0, s1 = 0, s2 = 0;        // batch 1: r,z,n
        {
            const unsigned xa = xB + (unsigned)(buf * (2 * XS * 4));
            u64 x0, x1, x2, x3, x4;
            lds_v2u64(x0, x1, xa);          // floats 0..3  (16B @ +0)
            lds_v2u64(x2, x3, xa + 16);     // floats 4..7  (16B @ +16)
            lds_u64(x4, xa + 32);           // floats 8..9  ( 8B @ +32)
            fma2(p0, wi[0][0], x0); fma2(p1, wi[1][0], x0); fma2(p2, wi[2][0], x0);
            fma2(p0, wi[0][1], x1); fma2(p1, wi[1][1], x1); fma2(p2, wi[2][1], x1);
            fma2(p0, wi[0][2], x2); fma2(p1, wi[1][2], x2); fma2(p2, wi[2][2], x2);
            fma2(p0, wi[0][3], x3); fma2(p1, wi[1][3], x3); fma2(p2, wi[2][3], x3);
            fma2(p0, wi[0][4], x4); fma2(p1, wi[1][4], x4); fma2(p2, wi[2][4], x4);
            const unsigned xb1 = xa + XS * 4;
            u64 y0, y1, y2, y3, y4;
            lds_v2u64(y0, y1, xb1);
            lds_v2u64(y2, y3, xb1 + 16);
            lds_u64(y4, xb1 + 32);
            fma2(s0, wi[0][0], y0); fma2(s1, wi[1][0], y0); fma2(s2, wi[2][0], y0);
            fma2(s0, wi[0][1], y1); fma2(s1, wi[1][1], y1); fma2(s2, wi[2][1], y1);
            fma2(s0, wi[0][2], y2); fma2(s1, wi[1][2], y2); fma2(s2, wi[2][2], y2);
            fma2(s0, wi[0][3], y3); fma2(s1, wi[1][3], y3); fma2(s2, wi[2][3], y3);
            fma2(s0, wi[0][4], y4); fma2(s1, wi[1][4], y4); fma2(s2, wi[2][4], y4);
        }
        const int bl = c & 1;
        // round 1 (xor 1): keep own batch, add partner's partial of own batch
        float a0 = bl ? hsum2(s0) : hsum2(p0);
        float a1 = bl ? hsum2(s1) : hsum2(p1);
        float a2 = bl ? hsum2(s2) : hsum2(p2);
        float o0 = bl ? hsum2(p0) : hsum2(s0);
        float o1 = bl ? hsum2(p1) : hsum2(s1);
        float o2 = bl ? hsum2(p2) : hsum2(s2);
        a0 += __shfl_xor_sync(smask, o0, 1);
        a1 += __shfl_xor_sync(smask, o1, 1);
        a2 += __shfl_xor_sync(smask, o2, 1);
        // round 2 (xor 2): same batch, other quarter pair
        a0 += __shfl_xor_sync(smask, a0, 2);
        a1 += __shfl_xor_sync(smask, a1, 2);
        a2 += __shfl_xor_sync(smask, a2, 2);
        g0 = a0; g1 = a1; g2 = a2;        // complete on lanes c<2 for batch c
    };

    // prologue: gi(0) -> gv
    float gv0, gv1, gv2;
    gi_compute(0, gv0, gv1, gv2);
    __syncthreads();   // prologue buf0 reads done before t=0 loader overwrites buf0

    float hprev = 0.0f, hs = 0.0f, hm = -1e30f;
    int bp = 0;

    for (int t = 0; t < T_STEPS; t++) {
        // loaders: issue x(t+2) global load early (clamped)
        float xr = 0.0f;
        if (xl) {
            int tf = (t + 2 < T_STEPS) ? (t + 2) : (T_STEPS - 1);
            xr = __ldg(xbase + (size_t)tf * XSTRIDE);
        }

        // gi(t+1) from x buf[(t+1)&1] (garbage-but-finite at t=999, unused)
        float gn0, gn1, gn2;
        gi_compute((t + 1) & 1, gn0, gn1, gn2);

        // h-dot partials: 3 gates x 2 batches, single accumulator each
        u64 a0 = 0, a1 = 0, a2 = 0, d0 = 0, d1 = 0, d2 = 0;
        {
            const unsigned ad = hB + bp * (2 * HP * 4);
            #pragma unroll
            for (int j = 0; j < CH / 4; j++) {           // 7 iters, 16B each
                u64 q0, q1, r0, r1;
                lds_v2u64(q0, q1, ad + j * 16);                  // batch 0
                lds_v2u64(r0, r1, ad + HP * 4 + j * 16);         // batch 1
                fma2(a0, w[0][2 * j], q0); fma2(a0, w[0][2 * j + 1], q1);
                fma2(a1, w[1][2 * j], q0); fma2(a1, w[1][2 * j + 1], q1);
                fma2(a2, w[2][2 * j], q0); fma2(a2, w[2][2 * j + 1], q1);
                fma2(d0, w[0][2 * j], r0); fma2(d0, w[0][2 * j + 1], r1);
                fma2(d1, w[1][2 * j], r0); fma2(d1, w[1][2 * j + 1], r1);
                fma2(d2, w[2][2 * j], r0); fma2(d2, w[2][2 * j + 1], r1);
            }
        }
        float s0b0 = hsum2(a0), s1b0 = hsum2(a1), s2b0 = hsum2(a2);
        float s0b1 = hsum2(d0), s1b1 = hsum2(d1), s2b1 = hsum2(d2);

        // quad reduction over chunks
        s0b0 += __shfl_xor_sync(smask, s0b0, 1); s0b0 += __shfl_xor_sync(smask, s0b0, 2);
        s1b0 += __shfl_xor_sync(smask, s1b0, 1); s1b0 += __shfl_xor_sync(smask, s1b0, 2);
        s2b0 += __shfl_xor_sync(smask, s2b0, 1); s2b0 += __shfl_xor_sync(smask, s2b0, 2);
        s0b1 += __shfl_xor_sync(smask, s0b1, 1); s0b1 += __shfl_xor_sync(smask, s0b1, 2);
        s1b1 += __shfl_xor_sync(smask, s1b1, 1); s1b1 += __shfl_xor_sync(smask, s1b1, 2);
        s2b1 += __shfl_xor_sync(smask, s2b1, 1); s2b1 += __shfl_xor_sync(smask, s2b1, 2);

        if (fin) {
            float hr = (c == 0) ? s0b0 : s0b1;
            float hz = (c == 0) ? s1b0 : s1b1;
            float hn = (c == 0) ? s2b0 : s2b1;
            float r = sigf(gv0 + bi0 + hr);
            float z = sigf(gv1 + bi1 + hz);
            float n = tanh_acc(gv2 + bi2 + r * (hn + bh2));
            float hnew = n + z * (hprev - n);
            hprev = hnew;
            hs += hnew;
            hm = fmaxf(hm, hnew);
            h_sh[1 - bp][c][h] = hnew;
        }
        gv0 = gn0; gv1 = gn1; gv2 = gn2;

        // loaders: publish x(t+2) into buf[t&1] (read at t+1 as buf[(t+2)&1])
        if (xl) x_sh[bp][xlb][xpos] = xr;

        __syncthreads();
        bp ^= 1;
    }

    // pooling features
    if (fin) {
        float inv = 1.0f / len0[b0 + c];
        feat_sh[c][h]     = hs * inv;
        feat_sh[c][H + h] = hm;
    }
    __syncthreads();

    // output linear: [2 x 20] = feat[2 x 200] @ W_out^T + b_out
    if (tid < 2 * NCLS) {
        int bb = tid / NCLS, cc = tid % NCLS;
        const float* wr = W_out + cc * 2 * H;
        float acc = b_out[cc];
        #pragma unroll 4
        for (int j = 0; j < 2 * H; j++) acc += feat_sh[bb][j] * wr[j];
        out[(b0 + bb) * NCLS + cc] = acc;
    }
}

extern "C" void kernel_launch(void* const* d_in, const int* in_sizes, int n_in,
                              void* d_out, int out_size)
{
    const float* mfcc0 = (const float*)d_in[0];
    const float* mfcc1 = (const float*)d_in[1];
    const float* mfcc2 = (const float*)d_in[2];
    const float* len0  = (const float*)d_in[3];
    const float* W_ih  = (const float*)d_in[4];
    const float* W_hh  = (const float*)d_in[5];
    const float* b_ih  = (const float*)d_in[6];
    const float* b_hh  = (const float*)d_in[7];
    const float* W_out = (const float*)d_in[8];
    const float* b_out = (const float*)d_in[9];
    float* out = (float*)d_out;

    gru_fused_kernel<<<B_TOT / 2, 400>>>(mfcc0, mfcc1, mfcc2, len0,
                                         W_ih, W_hh, b_ih, b_hh,
                                         W_out, b_out, out);
}

// round 14
// speedup vs baseline: 2.1634x; 1.8496x over previous
#include <cuda_runtime.h>

#define T_STEPS 1000
#define B_TOT   256
#define FIN     39
#define H       100
#define G3      300
#define NCLS    20
#define GSTR    (B_TOT * G3)

typedef unsigned long long u64;

// 307 MB scratch for precomputed input gates gi[t][b][g] (includes b_ih)
__device__ float g_gi[(size_t)T_STEPS * B_TOT * G3];

__device__ __forceinline__ u64 pk(float x, float y) {
    u64 r; asm("mov.b64 %0,{%1,%2};" : "=l"(r) : "f"(x), "f"(y)); return r;
}
__device__ __forceinline__ void fma2(u64 &d, u64 a, u64 b) {
    asm("fma.rn.f32x2 %0,%1,%2,%0;" : "+l"(d) : "l"(a), "l"(b));
}
__device__ __forceinline__ u64 add2(u64 a, u64 b) {
    u64 r; asm("add.rn.f32x2 %0,%1,%2;" : "=l"(r) : "l"(a), "l"(b)); return r;
}
__device__ __forceinline__ float hsum2(u64 a) {
    float x, y; asm("mov.b64 {%0,%1},%2;" : "=f"(x), "=f"(y) : "l"(a)); return x + y;
}
__device__ __forceinline__ void lds_v2u64(u64 &a, u64 &b, unsigned addr) {
    asm volatile("ld.shared.v2.u64 {%0,%1},[%2];" : "=l"(a), "=l"(b) : "r"(addr));
}
__device__ __forceinline__ float sigf(float x) {
    return __fdividef(1.0f, 1.0f + __expf(-x));
}
__device__ __forceinline__ float tanh_acc(float x) {
    return 2.0f * sigf(2.0f * x) - 1.0f;
}

// ---------------------------------------------------------------------------
// Kernel 1: gi[t][b][g] = b_ih[g] + sum_k x[t][b][k] * W_ih[g][k]
// pairs p = t*B + b processed in tiles of 32; W_ih rows persistent in regs.
// occupancy 3 (was 2): +50% warps to hide CTA-start weight LDG + STG latency.
// ---------------------------------------------------------------------------
#define K1_PAIRS 64
#define K1_TILE  32

__global__ void __launch_bounds__(320, 3) gi_precompute_kernel(
    const float* __restrict__ mfcc0, const float* __restrict__ mfcc1,
    const float* __restrict__ mfcc2,
    const float* __restrict__ W_ih, const float* __restrict__ b_ih)
{
    __shared__ __align__(16) float xt[2][K1_TILE][40];
    const int tid = threadIdx.x;
    const int g = (tid < G3) ? tid : (G3 - 1);

    u64 wih[20];
    {
        const float* w = W_ih + g * FIN;
        #pragma unroll
        for (int j = 0; j < 19; j++) wih[j] = pk(w[2 * j], w[2 * j + 1]);
        wih[19] = pk(w[38], 0.0f);
    }
    const float bias = b_ih[g];
    const int p0 = blockIdx.x * K1_PAIRS;

    // fill assignment: each thread owns 4 slots of the 1280-float tile
    int fpair[4], fk[4];
    const float* fptr[4];
    bool fok[4];
    #pragma unroll
    for (int s = 0; s < 4; s++) {
        int idx = tid + s * 320;
        int pr = idx / 40, k = idx - pr * 40;
        fpair[s] = pr; fk[s] = k;
        fok[s] = (k < 39);
        const float* src = (k < 13) ? mfcc0 : (k < 26) ? mfcc1 : mfcc2;
        int f = (k < 13) ? k : (k < 26) ? (k - 13) : (k - 26);
        fptr[s] = src + (size_t)(p0 + pr) * 13 + f;
    }

    // prologue: tile 0
    #pragma unroll
    for (int s = 0; s < 4; s++)
        xt[0][fpair[s]][fk[s]] = fok[s] ? __ldg(fptr[s]) : 0.0f;
    __syncthreads();

    const unsigned xB0 = (unsigned)__cvta_generic_to_shared(&xt[0][0][0]);

    for (int tile = 0; tile < K1_PAIRS / K1_TILE; tile++) {
        // issue loads for next tile into the other buffer
        if (tile + 1 < K1_PAIRS / K1_TILE) {
            #pragma unroll
            for (int s = 0; s < 4; s++) {
                fptr[s] += K1_TILE * 13;
                xt[(tile + 1) & 1][fpair[s]][fk[s]] = fok[s] ? __ldg(fptr[s]) : 0.0f;
            }
        }
        const unsigned xB = xB0 + (tile & 1) * (K1_TILE * 40 * 4);
        const int pb = p0 + tile * K1_TILE;
        #pragma unroll 2
        for (int pair = 0; pair < K1_TILE; pair += 2) {
            u64 a0 = 0, a1 = 0, c0 = 0, c1 = 0;
            unsigned ad = xB + pair * 160;
            #pragma unroll
            for (int j = 0; j < 10; j++) {
                u64 p, q, p2, q2;
                lds_v2u64(p,  q,  ad + j * 16);
                lds_v2u64(p2, q2, ad + 160 + j * 16);
                fma2(a0, wih[2 * j],     p);
                fma2(a1, wih[2 * j + 1], q);
                fma2(c0, wih[2 * j],     p2);
                fma2(c1, wih[2 * j + 1], q2);
            }
            if (tid < G3) {
                g_gi[(size_t)(pb + pair) * G3 + g]     = hsum2(add2(a0, a1)) + bias;
                g_gi[(size_t)(pb + pair + 1) * G3 + g] = hsum2(add2(c0, c1)) + bias;
            }
        }
        __syncthreads();
    }
}

// ---------------------------------------------------------------------------
// Kernel 2 (verbatim R3, measured 931us): persistent recurrent GRU.
// 128 CTAs x 400 threads. thread = (h = tid>>2, chunk c = tid&3). Each thread
// computes r,z,n gate partials for its h over K-chunk [c*28, c*28+28)
// (zero-padded), both batches. Quad bfly-reduction; lanes c<2 finalize
// batch b=c fully in registers. h double-buffered -> ONE barrier per step.
// ---------------------------------------------------------------------------
#define CH  28          // chunk floats (112B, 16B-aligned)
#define HP  112         // padded h per batch

__global__ void __launch_bounds__(400, 1) gru_rec_kernel(
    const float* __restrict__ len0,
    const float* __restrict__ W_hh, const float* __restrict__ b_hh,
    const float* __restrict__ W_out, const float* __restrict__ b_out,
    float* __restrict__ out)
{
    __shared__ __align__(16) float h_sh[2][2][HP];   // [buf][batch][v], pads zero
    __shared__ float feat_sh[2][2 * H];

    const int tid = threadIdx.x;
    const int h   = tid >> 2;          // 0..99
    const int c   = tid & 3;           // K-chunk, and batch selector for c<2
    const int b0  = blockIdx.x * 2;
    const unsigned smask = (tid < 384) ? 0xFFFFFFFFu : 0x0000FFFFu;

    // zero both h buffers (incl pads)
    for (int i = tid; i < 2 * 2 * HP; i += blockDim.x) ((float*)h_sh)[i] = 0.0f;

    // persistent W_hh chunk rows for 3 gates (r,z,n), zero-padded
    const int k0   = c * CH;
    const int kcnt = (k0 + CH <= H) ? CH : (H - k0);   // 28 or 16
    u64 w[3][CH / 2];
    #pragma unroll
    for (int i = 0; i < 3; i++) {
        const float* wr = W_hh + (h + i * H) * H + k0;
        #pragma unroll
        for (int j = 0; j < CH / 2; j++) {
            float x0 = (2 * j     < kcnt) ? wr[2 * j]     : 0.0f;
            float x1 = (2 * j + 1 < kcnt) ? wr[2 * j + 1] : 0.0f;
            w[i][j] = pk(x0, x1);
        }
    }

    // finalize-lane state (c < 2, batch b = c)
    const bool fin = (c < 2);
    float bh0 = 0.0f, bh1 = 0.0f, bh2 = 0.0f;
    const float* gp = g_gi;
    if (fin) {
        bh0 = b_hh[h]; bh1 = b_hh[h + H]; bh2 = b_hh[h + 2 * H];
        gp = g_gi + (size_t)(b0 + c) * G3 + h;
    }
    float hprev = 0.0f, hs = 0.0f, hm = -1e30f;

    // prefetch gi(t=0)
    float gv0 = 0.0f, gv1 = 0.0f, gv2 = 0.0f;
    if (fin) { gv0 = __ldg(gp); gv1 = __ldg(gp + H); gv2 = __ldg(gp + 2 * H); }

    const unsigned hB = (unsigned)__cvta_generic_to_shared(&h_sh[0][0][0]) + c * (CH * 4);
    int p = 0;
    __syncthreads();

    for (int t = 0; t < T_STEPS; t++) {
        // prefetch gi(t+1) ~1.5 steps before use
        float gn0 = 0.0f, gn1 = 0.0f, gn2 = 0.0f;
        if (fin && t + 1 < T_STEPS) {
            const float* gq = gp + (size_t)(t + 1) * GSTR;
            gn0 = __ldg(gq); gn1 = __ldg(gq + H); gn2 = __ldg(gq + 2 * H);
        }

        // partial dots: 3 gates x 2 batches, 2 accumulators each
        u64 a00 = 0, a01 = 0, a10 = 0, a11 = 0, a20 = 0, a21 = 0;   // batch 0
        u64 d00 = 0, d01 = 0, d10 = 0, d11 = 0, d20 = 0, d21 = 0;   // batch 1
        {
            const unsigned ad = hB + p * (2 * HP * 4);
            #pragma unroll
            for (int j = 0; j < CH / 4; j++) {           // 7 iters, 16B each
                u64 q0, q1, r0, r1;
                lds_v2u64(q0, q1, ad + j * 16);                  // batch 0
                lds_v2u64(r0, r1, ad + HP * 4 + j * 16);         // batch 1
                fma2(a00, w[0][2 * j], q0); fma2(a01, w[0][2 * j + 1], q1);
                fma2(a10, w[1][2 * j], q0); fma2(a11, w[1][2 * j + 1], q1);
                fma2(a20, w[2][2 * j], q0); fma2(a21, w[2][2 * j + 1], q1);
                fma2(d00, w[0][2 * j], r0); fma2(d01, w[0][2 * j + 1], r1);
                fma2(d10, w[1][2 * j], r0); fma2(d11, w[1][2 * j + 1], r1);
                fma2(d20, w[2][2 * j], r0); fma2(d21, w[2][2 * j + 1], r1);
            }
        }
        float s0b0 = hsum2(add2(a00, a01));
        float s1b0 = hsum2(add2(a10, a11));
        float s2b0 = hsum2(add2(a20, a21));
        float s0b1 = hsum2(add2(d00, d01));
        float s1b1 = hsum2(add2(d10, d11));
        float s2b1 = hsum2(add2(d20, d21));

        // quad reduction over chunks
        s0b0 += __shfl_xor_sync(smask, s0b0, 1); s0b0 += __shfl_xor_sync(smask, s0b0, 2);
        s1b0 += __shfl_xor_sync(smask, s1b0, 1); s1b0 += __shfl_xor_sync(smask, s1b0, 2);
        s2b0 += __shfl_xor_sync(smask, s2b0, 1); s2b0 += __shfl_xor_sync(smask, s2b0, 2);
        s0b1 += __shfl_xor_sync(smask, s0b1, 1); s0b1 += __shfl_xor_sync(smask, s0b1, 2);
        s1b1 += __shfl_xor_sync(smask, s1b1, 1); s1b1 += __shfl_xor_sync(smask, s1b1, 2);
        s2b1 += __shfl_xor_sync(smask, s2b1, 1); s2b1 += __shfl_xor_sync(smask, s2b1, 2);

        if (fin) {
            float hr = (c == 0) ? s0b0 : s0b1;
            float hz = (c == 0) ? s1b0 : s1b1;
            float hn = (c == 0) ? s2b0 : s2b1;
            float r = sigf(gv0 + hr + bh0);
            float z = sigf(gv1 + hz + bh1);
            float n = tanh_acc(gv2 + r * (hn + bh2));
            float hnew = n + z * (hprev - n);
            hprev = hnew;
            hs += hnew;
            hm = fmaxf(hm, hnew);
            h_sh[1 - p][c][h] = hnew;
        }
        gv0 = gn0; gv1 = gn1; gv2 = gn2;
        __syncthreads();
        p ^= 1;
    }

    // pooling features
    if (fin) {
        float inv = 1.0f / len0[b0 + c];
        feat_sh[c][h]     = hs * inv;
        feat_sh[c][H + h] = hm;
    }
    __syncthreads();

    // output linear: [2 x 20] = feat[2 x 200] @ W_out^T + b_out
    if (tid < 2 * NCLS) {
        int bb = tid / NCLS, cc = tid % NCLS;
        const float* wr = W_out + cc * 2 * H;
        float acc = b_out[cc];
        #pragma unroll 4
        for (int j = 0; j < 2 * H; j++) acc += feat_sh[bb][j] * wr[j];
        out[(b0 + bb) * NCLS + cc] = acc;
    }
}

extern "C" void kernel_launch(void* const* d_in, const int* in_sizes, int n_in,
                              void* d_out, int out_size)
{
    const float* mfcc0 = (const float*)d_in[0];
    const float* mfcc1 = (const float*)d_in[1];
    const float* mfcc2 = (const float*)d_in[2];
    const float* len0  = (const float*)d_in[3];
    const float* W_ih  = (const float*)d_in[4];
    const float* W_hh  = (const float*)d_in[5];
    const float* b_ih  = (const float*)d_in[6];
    const float* b_hh  = (const float*)d_in[7];
    const float* W_out = (const float*)d_in[8];
    const float* b_out = (const float*)d_in[9];
    float* out = (float*)d_out;

    gi_precompute_kernel<<<(T_STEPS * B_TOT) / K1_PAIRS, 320>>>(
        mfcc0, mfcc1, mfcc2, W_ih, b_ih);
    gru_rec_kernel<<<B_TOT / 2, 400>>>(len0, W_hh, b_hh, W_out, b_out, out);
}